// round 1
// baseline (speedup 1.0000x reference)
#include <cuda_runtime.h>
#include <math.h>

// Problem constants (from reference)
#define NN0 3072000
#define NN1 204800
#define NN2 20480
#define NN3 4096
#define EE0 3072000
#define EE1 204800
#define EE2 20480
#define DIN 100
#define DH  256
#define DOUT 47

// ---------------- device scratch (no allocations allowed) ----------------
__device__ float g_acc0[(size_t)NN1 * DIN];   // 81.9 MB
__device__ float g_cnt0[NN1];
__device__ float g_h1[(size_t)NN1 * DH];      // 209.7 MB
__device__ float g_acc1[(size_t)NN2 * DH];    // 21 MB
__device__ float g_cnt1[NN2];
__device__ float g_h2[(size_t)NN2 * DH];      // 21 MB
__device__ float g_acc2[(size_t)NN3 * DH];    // 4.2 MB
__device__ float g_cnt2[NN3];

// ---------------- helpers ----------------
__device__ __forceinline__ void red_add_v4(float* addr, float4 v) {
    asm volatile("red.global.add.v4.f32 [%0], {%1,%2,%3,%4};"
                 :: "l"(addr), "f"(v.x), "f"(v.y), "f"(v.z), "f"(v.w)
                 : "memory");
}

__global__ void zero4_kernel(float4* __restrict__ p, long n4) {
    long i = (long)blockIdx.x * blockDim.x + threadIdx.x;
    if (i < n4) p[i] = make_float4(0.f, 0.f, 0.f, 0.f);
}

// ---------------- layer-0 scatter: rows of 100 floats (25 float4) ----------------
// 32 lanes per edge; lanes 0..24 each RED one float4, lane 25 counts.
__global__ void scatter100(const float* __restrict__ x,
                           const int* __restrict__ src,
                           const int* __restrict__ dst,
                           float* __restrict__ acc,
                           float* __restrict__ cnt) {
    unsigned long long gid = (unsigned long long)blockIdx.x * blockDim.x + threadIdx.x;
    unsigned e = (unsigned)(gid >> 5);
    if (e >= EE0) return;
    int lane = (int)(gid & 31);
    int s = __ldg(src + e);
    int d = __ldg(dst + e);
    if (lane < 25) {
        float4 v = __ldg((const float4*)(x + (size_t)s * DIN) + lane);
        red_add_v4(acc + (size_t)d * DIN + lane * 4, v);
    } else if (lane == 25) {
        atomicAdd(cnt + d, 1.0f);
    }
}

// ---------------- scatter for 256-wide rows (64 float4), 64 lanes/edge ----------------
__global__ void scatter256(const float* __restrict__ h,
                           const int* __restrict__ src,
                           const int* __restrict__ dst,
                           float* __restrict__ acc,
                           float* __restrict__ cnt,
                           int E) {
    unsigned long long gid = (unsigned long long)blockIdx.x * blockDim.x + threadIdx.x;
    unsigned e = (unsigned)(gid >> 6);
    if (e >= (unsigned)E) return;
    int lane = (int)(gid & 63);
    int s = __ldg(src + e);
    int d = __ldg(dst + e);
    float4 v = __ldg((const float4*)(h + (size_t)s * DH) + lane);
    red_add_v4(acc + (size_t)d * DH + lane * 4, v);
    if (lane == 0) atomicAdd(cnt + d, 1.0f);
}

// ---------------- fused layer: out = relu((acc/max(cnt,1)) @ Wl + bias + self @ Wr) ----
// N fixed = 256. Tile: BM=64 rows x 256 cols, BK=32, 512 threads.
// thread t: ct = t&63 -> cols 4ct..4ct+3 ; rt = t>>6 -> rows rt+8j, j=0..7.
#define BM 64
#define BK 32

__global__ __launch_bounds__(512) void fused_layer(
    const float* __restrict__ acc, const float* __restrict__ cnt,
    const float* __restrict__ self, const float* __restrict__ Wl,
    const float* __restrict__ Wr, const float* __restrict__ bias,
    float* __restrict__ out, int M, int Ka)
{
    __shared__ __align__(16) float Ws[BK * 256];        // 32 KB
    __shared__ float As[BK * (BM + 1)];                 // 8.3 KB, [k][row]

    const int t = threadIdx.x;
    const int ct = t & 63;
    const int rt = t >> 6;
    const int rowbase = blockIdx.x * BM;

    float C[8][4];
#pragma unroll
    for (int j = 0; j < 8; j++) { C[j][0] = C[j][1] = C[j][2] = C[j][3] = 0.f; }

    for (int phase = 0; phase < 2; ++phase) {
        const float* A = phase ? self : acc;
        const float* W = phase ? Wr : Wl;
        for (int kc = 0; kc < Ka; kc += BK) {
            __syncthreads();
            // load W tile: BK x 256 floats = 2048 float4, 4 per thread
#pragma unroll
            for (int i = 0; i < 4; i++) {
                int idx4 = t + i * 512;
                int k = idx4 >> 6;
                int c4 = idx4 & 63;
                int gk = kc + k;
                float4 v = make_float4(0.f, 0.f, 0.f, 0.f);
                if (gk < Ka) v = *(const float4*)(W + (size_t)gk * 256 + c4 * 4);
                *(float4*)(Ws + (size_t)k * 256 + c4 * 4) = v;
            }
            // load A tile transposed: As[k][row], 2048 elements, 4 per thread
#pragma unroll
            for (int i = 0; i < 4; i++) {
                int idx = t + i * 512;
                int k = idx & 31;
                int row = idx >> 5;
                int gr = rowbase + row;
                int gk = kc + k;
                float v = 0.f;
                if (gr < M && gk < Ka) {
                    v = A[(size_t)gr * Ka + gk];
                    if (phase == 0) v = v / fmaxf(__ldg(cnt + gr), 1.0f);
                }
                As[k * (BM + 1) + row] = v;
            }
            __syncthreads();
#pragma unroll 8
            for (int k = 0; k < BK; k++) {
                float4 w = *(const float4*)(Ws + k * 256 + ct * 4);
#pragma unroll
                for (int j = 0; j < 8; j++) {
                    float a = As[k * (BM + 1) + rt + 8 * j];
                    C[j][0] = fmaf(a, w.x, C[j][0]);
                    C[j][1] = fmaf(a, w.y, C[j][1]);
                    C[j][2] = fmaf(a, w.z, C[j][2]);
                    C[j][3] = fmaf(a, w.w, C[j][3]);
                }
            }
        }
    }

    float4 b = *(const float4*)(bias + ct * 4);
#pragma unroll
    for (int j = 0; j < 8; j++) {
        int gr = rowbase + rt + 8 * j;
        if (gr < M) {
            float4 o;
            o.x = fmaxf(C[j][0] + b.x, 0.f);
            o.y = fmaxf(C[j][1] + b.y, 0.f);
            o.z = fmaxf(C[j][2] + b.z, 0.f);
            o.w = fmaxf(C[j][3] + b.w, 0.f);
            *(float4*)(out + (size_t)gr * 256 + ct * 4) = o;
        }
    }
}

// ---------------- final layer: K=512 concat GEMV per row + log_softmax over 47 ------
__global__ __launch_bounds__(64) void final_layer(
    const float* __restrict__ acc, const float* __restrict__ cnt,
    const float* __restrict__ self, const float* __restrict__ Wl,
    const float* __restrict__ bias, const float* __restrict__ Wr,
    float* __restrict__ out)
{
    __shared__ float sa[DH];
    __shared__ float ss[DH];
    __shared__ float logits[DOUT];
    __shared__ float red2[2];

    const int r = blockIdx.x;
    const int t = threadIdx.x;
    float c = fmaxf(__ldg(cnt + r), 1.0f);

    for (int k = t; k < DH; k += 64) {
        sa[k] = acc[(size_t)r * DH + k] / c;
        ss[k] = self[(size_t)r * DH + k];
    }
    __syncthreads();

    if (t < DOUT) {
        float v = __ldg(bias + t);
#pragma unroll 8
        for (int k = 0; k < DH; k++) {
            v = fmaf(sa[k], __ldg(Wl + (size_t)k * DOUT + t), v);
            v = fmaf(ss[k], __ldg(Wr + (size_t)k * DOUT + t), v);
        }
        logits[t] = v;
    }
    __syncthreads();
    if (t == 0) {
        float m = -1e30f;
        for (int i = 0; i < DOUT; i++) m = fmaxf(m, logits[i]);
        float s = 0.f;
        for (int i = 0; i < DOUT; i++) s += expf(logits[i] - m);
        red2[0] = m;
        red2[1] = logf(s);
    }
    __syncthreads();
    if (t < DOUT) out[(size_t)r * DOUT + t] = logits[t] - red2[0] - red2[1];
}

// ---------------- launch ----------------
extern "C" void kernel_launch(void* const* d_in, const int* in_sizes, int n_in,
                              void* d_out, int out_size) {
    const float* x    = (const float*)d_in[0];
    const int*   src0 = (const int*)d_in[1];
    const int*   dst0 = (const int*)d_in[2];
    const int*   src1 = (const int*)d_in[3];
    const int*   dst1 = (const int*)d_in[4];
    const int*   src2 = (const int*)d_in[5];
    const int*   dst2 = (const int*)d_in[6];
    const float* Wl0  = (const float*)d_in[7];
    const float* bl0  = (const float*)d_in[8];
    const float* Wr0  = (const float*)d_in[9];
    const float* Wl1  = (const float*)d_in[10];
    const float* bl1  = (const float*)d_in[11];
    const float* Wr1  = (const float*)d_in[12];
    const float* Wl2  = (const float*)d_in[13];
    const float* bl2  = (const float*)d_in[14];
    const float* Wr2  = (const float*)d_in[15];
    float* out = (float*)d_out;

    float *acc0, *cnt0, *h1, *acc1, *cnt1, *h2, *acc2, *cnt2;
    cudaGetSymbolAddress((void**)&acc0, g_acc0);
    cudaGetSymbolAddress((void**)&cnt0, g_cnt0);
    cudaGetSymbolAddress((void**)&h1,   g_h1);
    cudaGetSymbolAddress((void**)&acc1, g_acc1);
    cudaGetSymbolAddress((void**)&cnt1, g_cnt1);
    cudaGetSymbolAddress((void**)&h2,   g_h2);
    cudaGetSymbolAddress((void**)&acc2, g_acc2);
    cudaGetSymbolAddress((void**)&cnt2, g_cnt2);

    // zero accumulators + counts
    {
        long n;
        n = (long)NN1 * DIN / 4; zero4_kernel<<<(unsigned)((n + 255) / 256), 256>>>((float4*)acc0, n);
        n = (long)NN1 / 4;       zero4_kernel<<<(unsigned)((n + 255) / 256), 256>>>((float4*)cnt0, n);
        n = (long)NN2 * DH / 4;  zero4_kernel<<<(unsigned)((n + 255) / 256), 256>>>((float4*)acc1, n);
        n = (long)NN2 / 4;       zero4_kernel<<<(unsigned)((n + 255) / 256), 256>>>((float4*)cnt1, n);
        n = (long)NN3 * DH / 4;  zero4_kernel<<<(unsigned)((n + 255) / 256), 256>>>((float4*)acc2, n);
        n = (long)NN3 / 4;       zero4_kernel<<<(unsigned)((n + 255) / 256), 256>>>((float4*)cnt2, n);
    }

    // layer 0
    {
        unsigned long long th = (unsigned long long)EE0 * 32;
        scatter100<<<(unsigned)((th + 255) / 256), 256>>>(x, src0, dst0, acc0, cnt0);
        fused_layer<<<NN1 / BM, 512>>>(acc0, cnt0, x, Wl0, Wr0, bl0, h1, NN1, DIN);
    }
    // layer 1
    {
        unsigned long long th = (unsigned long long)EE1 * 64;
        scatter256<<<(unsigned)((th + 255) / 256), 256>>>(h1, src1, dst1, acc1, cnt1, EE1);
        fused_layer<<<NN2 / BM, 512>>>(acc1, cnt1, h1, Wl1, Wr1, bl1, h2, NN2, DH);
    }
    // layer 2 + log_softmax
    {
        unsigned long long th = (unsigned long long)EE2 * 64;
        scatter256<<<(unsigned)((th + 255) / 256), 256>>>(h2, src2, dst2, acc2, cnt2, EE2);
        final_layer<<<NN3, 64>>>(acc2, cnt2, h2, Wl2, bl2, Wr2, out);
    }
}

// round 3
// speedup vs baseline: 1.1345x; 1.1345x over previous
#include <cstdint>
#include <cuda_runtime.h>
#include <cuda_fp16.h>
#include <math.h>

typedef unsigned int u32;

#define NN0 3072000
#define NN1 204800
#define NN2 20480
#define NN3 4096
#define EE0 3072000
#define EE1 204800
#define EE2 20480
#define DIN 100
#define DH  256
#define DOUT 47

// ---------------- device scratch ----------------
__device__ float g_acc0[(size_t)NN1 * DIN];
__device__ float g_cnt0[NN1];
__device__ float g_h1[(size_t)NN1 * DH];
__device__ float g_acc1[(size_t)NN2 * DH];
__device__ float g_cnt1[NN2];
__device__ float g_h2[(size_t)NN2 * DH];
__device__ float g_acc2[(size_t)NN3 * DH];
__device__ float g_cnt2[NN3];

// ---------------- helpers ----------------
__device__ __forceinline__ void red_add_v4(float* addr, float4 v) {
    asm volatile("red.global.add.v4.f32 [%0], {%1,%2,%3,%4};"
                 :: "l"(addr), "f"(v.x), "f"(v.y), "f"(v.z), "f"(v.w)
                 : "memory");
}

__global__ void zero4_kernel(float4* __restrict__ p, long n4) {
    long i = (long)blockIdx.x * blockDim.x + threadIdx.x;
    if (i < n4) p[i] = make_float4(0.f, 0.f, 0.f, 0.f);
}

// ---------------- layer-0 scatter ----------------
__global__ void scatter100(const float* __restrict__ x,
                           const int* __restrict__ src,
                           const int* __restrict__ dst,
                           float* __restrict__ acc,
                           float* __restrict__ cnt) {
    unsigned long long gid = (unsigned long long)blockIdx.x * blockDim.x + threadIdx.x;
    unsigned e = (unsigned)(gid >> 5);
    if (e >= EE0) return;
    int lane = (int)(gid & 31);
    int s = __ldg(src + e);
    int d = __ldg(dst + e);
    if (lane < 25) {
        float4 v = __ldg((const float4*)(x + (size_t)s * DIN) + lane);
        red_add_v4(acc + (size_t)d * DIN + lane * 4, v);
    } else if (lane == 25) {
        atomicAdd(cnt + d, 1.0f);
    }
}

__global__ void scatter256(const float* __restrict__ h,
                           const int* __restrict__ src,
                           const int* __restrict__ dst,
                           float* __restrict__ acc,
                           float* __restrict__ cnt,
                           int E) {
    unsigned long long gid = (unsigned long long)blockIdx.x * blockDim.x + threadIdx.x;
    unsigned e = (unsigned)(gid >> 6);
    if (e >= (unsigned)E) return;
    int lane = (int)(gid & 63);
    int s = __ldg(src + e);
    int d = __ldg(dst + e);
    float4 v = __ldg((const float4*)(h + (size_t)s * DH) + lane);
    red_add_v4(acc + (size_t)d * DH + lane * 4, v);
    if (lane == 0) atomicAdd(cnt + d, 1.0f);
}

// ---------------- tensor-core fused layer ----------------
// out[M,256] = relu( (acc/max(cnt,1)) @ Wl + bias + self @ Wr )
// HMMA m16n8k16 with 3xfp16 error-split (hi*hi + hi*lo + lo*hi), fp32 accum.
// Block: 256 thr (8 warps, 4x2). BM=128, BN=64, BK=32. grid=(M/128, 4).

#define LDA 40   // 32 + 8 halves padding: 80B row stride, 16B-aligned, LDSM conflict-free

__device__ __forceinline__ u32 smem_u32p(const void* p) {
    return (u32)__cvta_generic_to_shared(p);
}

__device__ __forceinline__ void ldsm4(u32* r, u32 addr) {
    asm volatile("ldmatrix.sync.aligned.m8n8.x4.shared.b16 {%0,%1,%2,%3}, [%4];"
                 : "=r"(r[0]), "=r"(r[1]), "=r"(r[2]), "=r"(r[3]) : "r"(addr));
}

__device__ __forceinline__ void mma16816(float* acc_, const u32* a, const u32* b) {
    asm volatile("mma.sync.aligned.m16n8k16.row.col.f32.f16.f16.f32 "
                 "{%0,%1,%2,%3}, {%4,%5,%6,%7}, {%8,%9}, {%0,%1,%2,%3};"
                 : "+f"(acc_[0]), "+f"(acc_[1]), "+f"(acc_[2]), "+f"(acc_[3])
                 : "r"(a[0]), "r"(a[1]), "r"(a[2]), "r"(a[3]), "r"(b[0]), "r"(b[1]));
}

__global__ __launch_bounds__(256) void fused_layer_mma(
    const float* __restrict__ acc, const float* __restrict__ cnt,
    const float* __restrict__ self, const float* __restrict__ Wl,
    const float* __restrict__ Wr, const float* __restrict__ bias,
    float* __restrict__ out, int Ka)
{
    __shared__ __align__(16) __half AsH[128 * LDA];
    __shared__ __align__(16) __half AsL[128 * LDA];
    __shared__ __align__(16) __half BsH[64 * LDA];
    __shared__ __align__(16) __half BsL[64 * LDA];

    const int t = threadIdx.x;
    const int lane = t & 31;
    const int wid = t >> 5;
    const int wm = (wid & 3) * 32;
    const int wn = (wid >> 2) * 32;
    const int rowbase = blockIdx.x * 128;
    const int nbase = blockIdx.y * 64;

    float cfrag[2][4][4];
#pragma unroll
    for (int m = 0; m < 2; m++) {
#pragma unroll
        for (int n = 0; n < 4; n++) {
#pragma unroll
            for (int i = 0; i < 4; i++) {
                cfrag[m][n][i] = 0.f;
            }
        }
    }

    for (int phase = 0; phase < 2; phase++) {
        const float* A = (phase != 0) ? self : acc;
        const float* W = (phase != 0) ? Wr : Wl;
        for (int kc = 0; kc < Ka; kc += 32) {
            __syncthreads();
            // load A tile 128x32 as hi/lo halves, scaled by 1/cnt in phase 0
#pragma unroll
            for (int i = 0; i < 4; i++) {
                int idx = t + i * 256;
                int r = idx >> 3;
                int k4 = (idx & 7) * 4;
                int gk = kc + k4;
                float4 v = make_float4(0.f, 0.f, 0.f, 0.f);
                if (gk < Ka) {
                    v = *(const float4*)(A + (size_t)(rowbase + r) * Ka + gk);
                }
                if (phase == 0) {
                    float ic = 1.0f / fmaxf(__ldg(cnt + rowbase + r), 1.0f);
                    v.x *= ic; v.y *= ic; v.z *= ic; v.w *= ic;
                }
                __half hx = __float2half_rn(v.x);
                __half hy = __float2half_rn(v.y);
                __half hz = __float2half_rn(v.z);
                __half hw = __float2half_rn(v.w);
                __half2* ph = (__half2*)(AsH + r * LDA + k4);
                ph[0] = __halves2half2(hx, hy);
                ph[1] = __halves2half2(hz, hw);
                __half lx = __float2half_rn(v.x - __half2float(hx));
                __half ly = __float2half_rn(v.y - __half2float(hy));
                __half lz = __float2half_rn(v.z - __half2float(hz));
                __half lw = __float2half_rn(v.w - __half2float(hw));
                __half2* pl = (__half2*)(AsL + r * LDA + k4);
                pl[0] = __halves2half2(lx, ly);
                pl[1] = __halves2half2(lz, lw);
            }
            // load W tile 32x64, transposed to [n][k], hi/lo
#pragma unroll
            for (int i = 0; i < 2; i++) {
                int idx = t + i * 256;
                int n4 = (idx & 15) * 4;
                int kk = idx >> 4;
                int gk = kc + kk;
                float4 w = make_float4(0.f, 0.f, 0.f, 0.f);
                if (gk < Ka) {
                    w = *(const float4*)(W + (size_t)gk * 256 + nbase + n4);
                }
                float wv[4];
                wv[0] = w.x; wv[1] = w.y; wv[2] = w.z; wv[3] = w.w;
#pragma unroll
                for (int j = 0; j < 4; j++) {
                    __half h = __float2half_rn(wv[j]);
                    __half l = __float2half_rn(wv[j] - __half2float(h));
                    BsH[(n4 + j) * LDA + kk] = h;
                    BsL[(n4 + j) * LDA + kk] = l;
                }
            }
            __syncthreads();
            // compute: 2 k16 steps per BK=32
#pragma unroll
            for (int ks = 0; ks < 2; ks++) {
                int arow = lane & 15;
                int koff = ks * 16 + ((lane >> 4) << 3);
                u32 aH[2][4];
                u32 aL[2][4];
                u32 bH[4][2];
                u32 bL[4][2];
#pragma unroll
                for (int m = 0; m < 2; m++) {
                    ldsm4(aH[m], smem_u32p(AsH + (wm + m * 16 + arow) * LDA + koff));
                    ldsm4(aL[m], smem_u32p(AsL + (wm + m * 16 + arow) * LDA + koff));
                }
#pragma unroll
                for (int nb = 0; nb < 2; nb++) {
                    u32 rh[4];
                    u32 rl[4];
                    ldsm4(rh, smem_u32p(BsH + (wn + nb * 16 + arow) * LDA + koff));
                    ldsm4(rl, smem_u32p(BsL + (wn + nb * 16 + arow) * LDA + koff));
                    bH[nb * 2][0] = rh[0]; bH[nb * 2][1] = rh[2];
                    bH[nb * 2 + 1][0] = rh[1]; bH[nb * 2 + 1][1] = rh[3];
                    bL[nb * 2][0] = rl[0]; bL[nb * 2][1] = rl[2];
                    bL[nb * 2 + 1][0] = rl[1]; bL[nb * 2 + 1][1] = rl[3];
                }
#pragma unroll
                for (int m = 0; m < 2; m++) {
#pragma unroll
                    for (int n = 0; n < 4; n++) {
                        mma16816(cfrag[m][n], aH[m], bH[n]);
                        mma16816(cfrag[m][n], aH[m], bL[n]);
                        mma16816(cfrag[m][n], aL[m], bH[n]);
                    }
                }
            }
        }
    }

    // epilogue: bias + relu
    const int rr = lane >> 2;
    const int cc = (lane & 3) * 2;
#pragma unroll
    for (int m = 0; m < 2; m++) {
#pragma unroll
        for (int n = 0; n < 4; n++) {
            int gcol = nbase + wn + n * 8 + cc;
            int grow = rowbase + wm + m * 16 + rr;
            float2 b2 = *(const float2*)(bias + gcol);
            float2 o0, o1;
            o0.x = fmaxf(cfrag[m][n][0] + b2.x, 0.f);
            o0.y = fmaxf(cfrag[m][n][1] + b2.y, 0.f);
            o1.x = fmaxf(cfrag[m][n][2] + b2.x, 0.f);
            o1.y = fmaxf(cfrag[m][n][3] + b2.y, 0.f);
            *(float2*)(out + (size_t)grow * 256 + gcol) = o0;
            *(float2*)(out + (size_t)(grow + 8) * 256 + gcol) = o1;
        }
    }
}

// ---------------- final layer: GEMV K=512 + log_softmax ----------------
__global__ __launch_bounds__(64) void final_layer(
    const float* __restrict__ acc, const float* __restrict__ cnt,
    const float* __restrict__ self, const float* __restrict__ Wl,
    const float* __restrict__ bias, const float* __restrict__ Wr,
    float* __restrict__ out)
{
    __shared__ float sa[DH];
    __shared__ float ss[DH];
    __shared__ float logits[DOUT];
    __shared__ float red2[2];

    const int r = blockIdx.x;
    const int t = threadIdx.x;
    float c = fmaxf(__ldg(cnt + r), 1.0f);

    for (int k = t; k < DH; k += 64) {
        sa[k] = acc[(size_t)r * DH + k] / c;
        ss[k] = self[(size_t)r * DH + k];
    }
    __syncthreads();

    if (t < DOUT) {
        float v = __ldg(bias + t);
#pragma unroll 8
        for (int k = 0; k < DH; k++) {
            v = fmaf(sa[k], __ldg(Wl + (size_t)k * DOUT + t), v);
            v = fmaf(ss[k], __ldg(Wr + (size_t)k * DOUT + t), v);
        }
        logits[t] = v;
    }
    __syncthreads();
    if (t == 0) {
        float m = -1e30f;
        for (int i = 0; i < DOUT; i++) {
            m = fmaxf(m, logits[i]);
        }
        float s = 0.f;
        for (int i = 0; i < DOUT; i++) {
            s += expf(logits[i] - m);
        }
        red2[0] = m;
        red2[1] = logf(s);
    }
    __syncthreads();
    if (t < DOUT) {
        out[(size_t)r * DOUT + t] = logits[t] - red2[0] - red2[1];
    }
}

// ---------------- launch ----------------
extern "C" void kernel_launch(void* const* d_in, const int* in_sizes, int n_in,
                              void* d_out, int out_size) {
    const float* x    = (const float*)d_in[0];
    const int*   src0 = (const int*)d_in[1];
    const int*   dst0 = (const int*)d_in[2];
    const int*   src1 = (const int*)d_in[3];
    const int*   dst1 = (const int*)d_in[4];
    const int*   src2 = (const int*)d_in[5];
    const int*   dst2 = (const int*)d_in[6];
    const float* Wl0  = (const float*)d_in[7];
    const float* bl0  = (const float*)d_in[8];
    const float* Wr0  = (const float*)d_in[9];
    const float* Wl1  = (const float*)d_in[10];
    const float* bl1  = (const float*)d_in[11];
    const float* Wr1  = (const float*)d_in[12];
    const float* Wl2  = (const float*)d_in[13];
    const float* bl2  = (const float*)d_in[14];
    const float* Wr2  = (const float*)d_in[15];
    float* out = (float*)d_out;

    float* acc0 = 0; float* cnt0 = 0; float* h1 = 0; float* acc1 = 0;
    float* cnt1 = 0; float* h2 = 0; float* acc2 = 0; float* cnt2 = 0;
    cudaGetSymbolAddress((void**)&acc0, g_acc0);
    cudaGetSymbolAddress((void**)&cnt0, g_cnt0);
    cudaGetSymbolAddress((void**)&h1,   g_h1);
    cudaGetSymbolAddress((void**)&acc1, g_acc1);
    cudaGetSymbolAddress((void**)&cnt1, g_cnt1);
    cudaGetSymbolAddress((void**)&h2,   g_h2);
    cudaGetSymbolAddress((void**)&acc2, g_acc2);
    cudaGetSymbolAddress((void**)&cnt2, g_cnt2);

    long n;
    n = (long)NN1 * DIN / 4; zero4_kernel<<<(unsigned)((n + 255) / 256), 256>>>((float4*)acc0, n);
    n = (long)NN1 / 4;       zero4_kernel<<<(unsigned)((n + 255) / 256), 256>>>((float4*)cnt0, n);
    n = (long)NN2 * DH / 4;  zero4_kernel<<<(unsigned)((n + 255) / 256), 256>>>((float4*)acc1, n);
    n = (long)NN2 / 4;       zero4_kernel<<<(unsigned)((n + 255) / 256), 256>>>((float4*)cnt1, n);
    n = (long)NN3 * DH / 4;  zero4_kernel<<<(unsigned)((n + 255) / 256), 256>>>((float4*)acc2, n);
    n = (long)NN3 / 4;       zero4_kernel<<<(unsigned)((n + 255) / 256), 256>>>((float4*)cnt2, n);

    unsigned long long th0 = (unsigned long long)EE0 * 32;
    scatter100<<<(unsigned)((th0 + 255) / 256), 256>>>(x, src0, dst0, acc0, cnt0);
    dim3 g0(NN1 / 128, 4);
    fused_layer_mma<<<g0, 256>>>(acc0, cnt0, x, Wl0, Wr0, bl0, h1, DIN);

    unsigned long long th1 = (unsigned long long)EE1 * 64;
    scatter256<<<(unsigned)((th1 + 255) / 256), 256>>>(h1, src1, dst1, acc1, cnt1, EE1);
    dim3 g1(NN2 / 128, 4);
    fused_layer_mma<<<g1, 256>>>(acc1, cnt1, h1, Wl1, Wr1, bl1, h2, DH);

    unsigned long long th2 = (unsigned long long)EE2 * 64;
    scatter256<<<(unsigned)((th2 + 255) / 256), 256>>>(h2, src2, dst2, acc2, cnt2, EE2);
    final_layer<<<NN3, 64>>>(acc2, cnt2, h2, Wl2, bl2, Wr2, out);
}

// round 4
// speedup vs baseline: 1.3432x; 1.1840x over previous
#include <cstdint>
#include <cuda_runtime.h>
#include <cuda_fp16.h>
#include <math.h>

typedef unsigned int u32;

#define NN0 3072000
#define NN1 204800
#define NN2 20480
#define NN3 4096
#define EE0 3072000
#define EE1 204800
#define EE2 20480
#define DIN 100
#define DH  256
#define DOUT 47
#define KP0 224     // layer0 concat-K: [0,100)=agg, [112,212)=self, rest 0
#define KP1 512     // layer1 concat-K: [0,256)=agg, [256,512)=self

// ---------------- device scratch ----------------
__device__ float  g_acc0[(size_t)NN1 * DIN];
__device__ float  g_cnt0[NN1];
__device__ __half g_A0H[(size_t)NN1 * KP0];
__device__ __half g_A0L[(size_t)NN1 * KP0];
__device__ __half g_h1H[(size_t)NN1 * DH];
__device__ __half g_h1L[(size_t)NN1 * DH];
__device__ float  g_acc1[(size_t)NN2 * DH];
__device__ float  g_cnt1[NN2];
__device__ __half g_A1H[(size_t)NN2 * KP1];
__device__ __half g_A1L[(size_t)NN2 * KP1];
__device__ __half g_h2H[(size_t)NN2 * DH];
__device__ __half g_h2L[(size_t)NN2 * DH];
__device__ float  g_acc2[(size_t)NN3 * DH];
__device__ float  g_cnt2[NN3];
__device__ __half g_W0H[256 * KP0];
__device__ __half g_W0L[256 * KP0];
__device__ __half g_W1H[256 * KP1];
__device__ __half g_W1L[256 * KP1];

// ---------------- small helpers ----------------
__device__ __forceinline__ void red_add_v4(float* addr, float4 v) {
    asm volatile("red.global.add.v4.f32 [%0], {%1,%2,%3,%4};"
                 :: "l"(addr), "f"(v.x), "f"(v.y), "f"(v.z), "f"(v.w)
                 : "memory");
}
__device__ __forceinline__ u32 smem_u32p(const void* p) {
    return (u32)__cvta_generic_to_shared(p);
}
__device__ __forceinline__ void cpa16(u32 saddr, const void* g) {
    asm volatile("cp.async.cg.shared.global [%0], [%1], 16;" :: "r"(saddr), "l"(g));
}
__device__ __forceinline__ void ldsm4(u32* r, u32 addr) {
    asm volatile("ldmatrix.sync.aligned.m8n8.x4.shared.b16 {%0,%1,%2,%3}, [%4];"
                 : "=r"(r[0]), "=r"(r[1]), "=r"(r[2]), "=r"(r[3]) : "r"(addr));
}
__device__ __forceinline__ void mma16816(float* acc_, const u32* a, const u32* b) {
    asm volatile("mma.sync.aligned.m16n8k16.row.col.f32.f16.f16.f32 "
                 "{%0,%1,%2,%3}, {%4,%5,%6,%7}, {%8,%9}, {%0,%1,%2,%3};"
                 : "+f"(acc_[0]), "+f"(acc_[1]), "+f"(acc_[2]), "+f"(acc_[3])
                 : "r"(a[0]), "r"(a[1]), "r"(a[2]), "r"(a[3]), "r"(b[0]), "r"(b[1]));
}
__device__ __forceinline__ void split2(float v, __half& h, __half& l) {
    h = __float2half_rn(v);
    l = __float2half_rn(v - __half2float(h));
}

// ---------------- launch 0: zero all accumulators/counters ----------------
#define Z0 ((long)NN1 * DIN / 4)
#define Z1 (NN1 / 4)
#define Z2 ((long)NN2 * DH / 4)
#define Z3 (NN2 / 4)
#define Z4 ((long)NN3 * DH / 4)
#define Z5 (NN3 / 4)
#define ZTOT (Z0 + Z1 + Z2 + Z3 + Z4 + Z5)

__global__ void zero_all(float4* acc0, float4* cnt0, float4* acc1,
                         float4* cnt1, float4* acc2, float4* cnt2) {
    long i = (long)blockIdx.x * blockDim.x + threadIdx.x;
    float4 z = make_float4(0.f, 0.f, 0.f, 0.f);
    if (i < Z0) { acc0[i] = z; return; }
    i -= Z0;
    if (i < Z1) { cnt0[i] = z; return; }
    i -= Z1;
    if (i < Z2) { acc1[i] = z; return; }
    i -= Z2;
    if (i < Z3) { cnt1[i] = z; return; }
    i -= Z3;
    if (i < Z4) { acc2[i] = z; return; }
    i -= Z4;
    if (i < Z5) { cnt2[i] = z; return; }
}

// ---------------- launch 1: build transposed concat weights (hi/lo) --------
__global__ void conv_w_all(const float* __restrict__ Wl0, const float* __restrict__ Wr0,
                           const float* __restrict__ Wl1, const float* __restrict__ Wr1,
                           __half* W0H, __half* W0L, __half* W1H, __half* W1L) {
    long total0 = 256L * KP0;
    long total1 = 256L * KP1;
    long i = (long)blockIdx.x * blockDim.x + threadIdx.x;
    if (i < total0) {
        int n = (int)(i / KP0);
        int k = (int)(i % KP0);
        float v = 0.f;
        if (k < 100) v = Wl0[(size_t)k * 256 + n];
        else if (k >= 112 && k < 212) v = Wr0[(size_t)(k - 112) * 256 + n];
        __half h, l;
        split2(v, h, l);
        W0H[i] = h; W0L[i] = l;
        return;
    }
    i -= total0;
    if (i < total1) {
        int n = (int)(i / KP1);
        int k = (int)(i % KP1);
        float v;
        if (k < 256) v = Wl1[(size_t)k * 256 + n];
        else v = Wr1[(size_t)(k - 256) * 256 + n];
        __half h, l;
        split2(v, h, l);
        W1H[i] = h; W1L[i] = l;
    }
}

// ---------------- launch 2: x self-part of A0 + zero padding ---------------
__global__ void conv_self0(const float* __restrict__ x, __half* AH, __half* AL) {
    long i = (long)blockIdx.x * blockDim.x + threadIdx.x;
    long ndata = (long)NN1 * 25;
    if (i < ndata) {
        int r = (int)(i / 25);
        int c4 = (int)(i % 25);
        float4 v = __ldg((const float4*)(x + (size_t)r * DIN) + c4);
        float vv[4] = {v.x, v.y, v.z, v.w};
        size_t base = (size_t)r * KP0 + 112 + c4 * 4;
#pragma unroll
        for (int j = 0; j < 4; j++) {
            __half h, l;
            split2(vv[j], h, l);
            AH[base + j] = h;
            AL[base + j] = l;
        }
        return;
    }
    i -= ndata;
    // padding: cols [100,112) and [212,224), as half2 (12 half2 per row)
    long npad = (long)NN1 * 12;
    if (i < npad) {
        int r = (int)(i / 12);
        int j = (int)(i % 12);
        int col = (j < 6) ? (100 + j * 2) : (200 + j * 2);
        __half2 z = __halves2half2(__float2half_rn(0.f), __float2half_rn(0.f));
        *(__half2*)(AH + (size_t)r * KP0 + col) = z;
        *(__half2*)(AL + (size_t)r * KP0 + col) = z;
    }
}

// ---------------- launch 3: layer-0 edge scatter ----------------
__global__ void scatter100(const float* __restrict__ x,
                           const int* __restrict__ src,
                           const int* __restrict__ dst,
                           float* __restrict__ acc,
                           float* __restrict__ cnt) {
    unsigned long long gid = (unsigned long long)blockIdx.x * blockDim.x + threadIdx.x;
    unsigned e = (unsigned)(gid >> 5);
    if (e >= EE0) return;
    int lane = (int)(gid & 31);
    int s = __ldg(src + e);
    int d = __ldg(dst + e);
    if (lane < 25) {
        float4 v = __ldg((const float4*)(x + (size_t)s * DIN) + lane);
        red_add_v4(acc + (size_t)d * DIN + lane * 4, v);
    } else if (lane == 25) {
        atomicAdd(cnt + d, 1.0f);
    }
}

// ---------------- launch 4: agg part of A0 (scale by 1/cnt, split) ---------
__global__ void conv_agg0(const float* __restrict__ acc, const float* __restrict__ cnt,
                          __half* AH, __half* AL) {
    long i = (long)blockIdx.x * blockDim.x + threadIdx.x;
    if (i >= (long)NN1 * 25) return;
    int r = (int)(i / 25);
    int c4 = (int)(i % 25);
    float ic = 1.0f / fmaxf(__ldg(cnt + r), 1.0f);
    float4 v = *((const float4*)(acc + (size_t)r * DIN) + c4);
    float vv[4] = {v.x * ic, v.y * ic, v.z * ic, v.w * ic};
    size_t base = (size_t)r * KP0 + c4 * 4;
#pragma unroll
    for (int j = 0; j < 4; j++) {
        __half h, l;
        split2(vv[j], h, l);
        AH[base + j] = h;
        AL[base + j] = l;
    }
}

// ---------------- GEMM: C = AH@WH + AH@WL + AL@WH, bias+relu, split out ----
// A: [M, Kpad] fp16 (hi/lo). W: [256, Kpad] fp16 (hi/lo, n-major = pre-transposed).
// Block 256 thr (8 warps 4x2), BM=128 BN=64 BK=32, 2-stage cp.async pipeline.
// grid = (4, M/128): adjacent CTAs share the same A tile -> L2 reuse.

#define LDA 40                 // halves per smem row (80 B): LDSM conflict-free
#define OFF_AH 0
#define OFF_AL (128 * LDA * 2)           // 10240
#define OFF_BH (OFF_AL + 128 * LDA * 2)  // 20480
#define OFF_BL (OFF_BH + 64 * LDA * 2)   // 25600
#define STAGE_BYTES (OFF_BL + 64 * LDA * 2)  // 30720
#define GEMM_SMEM (2 * STAGE_BYTES)          // 61440

extern __shared__ char dsm[];

__global__ __launch_bounds__(256, 2) void gemm_hl(
    const __half* __restrict__ AH, const __half* __restrict__ AL,
    const __half* __restrict__ WH, const __half* __restrict__ WL,
    const float* __restrict__ bias,
    __half* __restrict__ outH, __half* __restrict__ outL, int Kpad)
{
    const int t = threadIdx.x;
    const int lane = t & 31;
    const int wid = t >> 5;
    const int wm = (wid & 3) * 32;
    const int wn = (wid >> 2) * 32;
    const int nbase = blockIdx.x * 64;
    const int rowbase = blockIdx.y * 128;
    const u32 sbase = smem_u32p(dsm);

    // per-thread cp.async source/dest precompute
    const int ar0 = t >> 2;          // A rows: t>>2 and (t+256)>>2 = ar0+64
    const int ac = (t & 3) * 8;      // k-chunk offset in halves
    const int br = t >> 2;           // B row (64 rows, t>>2 < 64 only for t<256: t>>2 in 0..63) 

    float cfrag[2][4][4];
#pragma unroll
    for (int m = 0; m < 2; m++)
#pragma unroll
        for (int n = 0; n < 4; n++)
#pragma unroll
            for (int i = 0; i < 4; i++) cfrag[m][n][i] = 0.f;

    const int KT = Kpad >> 5;

    // ---- issue stage 0
    {
        u32 sb = sbase;
        size_t ga = (size_t)(rowbase + ar0) * Kpad + ac;
        cpa16(sb + OFF_AH + (ar0 * LDA + ac) * 2, AH + ga);
        cpa16(sb + OFF_AL + (ar0 * LDA + ac) * 2, AL + ga);
        size_t ga2 = (size_t)(rowbase + ar0 + 64) * Kpad + ac;
        cpa16(sb + OFF_AH + ((ar0 + 64) * LDA + ac) * 2, AH + ga2);
        cpa16(sb + OFF_AL + ((ar0 + 64) * LDA + ac) * 2, AL + ga2);
        size_t gb = (size_t)(nbase + br) * Kpad + ac;
        cpa16(sb + OFF_BH + (br * LDA + ac) * 2, WH + gb);
        cpa16(sb + OFF_BL + (br * LDA + ac) * 2, WL + gb);
        asm volatile("cp.async.commit_group;");
    }

    for (int kt = 0; kt < KT; kt++) {
        asm volatile("cp.async.wait_group 0;");
        __syncthreads();
        if (kt + 1 < KT) {
            u32 sb = sbase + ((kt + 1) & 1) * STAGE_BYTES;
            int kc = (kt + 1) << 5;
            size_t ga = (size_t)(rowbase + ar0) * Kpad + kc + ac;
            cpa16(sb + OFF_AH + (ar0 * LDA + ac) * 2, AH + ga);
            cpa16(sb + OFF_AL + (ar0 * LDA + ac) * 2, AL + ga);
            size_t ga2 = (size_t)(rowbase + ar0 + 64) * Kpad + kc + ac;
            cpa16(sb + OFF_AH + ((ar0 + 64) * LDA + ac) * 2, AH + ga2);
            cpa16(sb + OFF_AL + ((ar0 + 64) * LDA + ac) * 2, AL + ga2);
            size_t gb = (size_t)(nbase + br) * Kpad + kc + ac;
            cpa16(sb + OFF_BH + (br * LDA + ac) * 2, WH + gb);
            cpa16(sb + OFF_BL + (br * LDA + ac) * 2, WL + gb);
            asm volatile("cp.async.commit_group;");
        }
        // ---- compute current stage
        u32 cb = sbase + (kt & 1) * STAGE_BYTES;
#pragma unroll
        for (int ks = 0; ks < 2; ks++) {
            int arow = lane & 15;
            int koff = ks * 16 + ((lane >> 4) << 3);
            u32 aH[2][4], aL[2][4], bH[4][2], bL[4][2];
#pragma unroll
            for (int m = 0; m < 2; m++) {
                ldsm4(aH[m], cb + OFF_AH + ((wm + m * 16 + arow) * LDA + koff) * 2);
                ldsm4(aL[m], cb + OFF_AL + ((wm + m * 16 + arow) * LDA + koff) * 2);
            }
#pragma unroll
            for (int nb = 0; nb < 2; nb++) {
                u32 rh[4], rl[4];
                ldsm4(rh, cb + OFF_BH + ((wn + nb * 16 + arow) * LDA + koff) * 2);
                ldsm4(rl, cb + OFF_BL + ((wn + nb * 16 + arow) * LDA + koff) * 2);
                bH[nb * 2][0] = rh[0]; bH[nb * 2][1] = rh[2];
                bH[nb * 2 + 1][0] = rh[1]; bH[nb * 2 + 1][1] = rh[3];
                bL[nb * 2][0] = rl[0]; bL[nb * 2][1] = rl[2];
                bL[nb * 2 + 1][0] = rl[1]; bL[nb * 2 + 1][1] = rl[3];
            }
#pragma unroll
            for (int m = 0; m < 2; m++)
#pragma unroll
                for (int n = 0; n < 4; n++) {
                    mma16816(cfrag[m][n], aH[m], bH[n]);
                    mma16816(cfrag[m][n], aH[m], bL[n]);
                    mma16816(cfrag[m][n], aL[m], bH[n]);
                }
        }
        __syncthreads();
    }

    // ---- epilogue: bias + relu, split to (hi,lo) halves
    const int rr = lane >> 2;
    const int cc = (lane & 3) * 2;
#pragma unroll
    for (int m = 0; m < 2; m++) {
#pragma unroll
        for (int n = 0; n < 4; n++) {
            int gcol = nbase + wn + n * 8 + cc;
            int grow = rowbase + wm + m * 16 + rr;
            float2 b2 = *(const float2*)(bias + gcol);
            float v00 = fmaxf(cfrag[m][n][0] + b2.x, 0.f);
            float v01 = fmaxf(cfrag[m][n][1] + b2.y, 0.f);
            float v10 = fmaxf(cfrag[m][n][2] + b2.x, 0.f);
            float v11 = fmaxf(cfrag[m][n][3] + b2.y, 0.f);
            __half h00, l00, h01, l01, h10, l10, h11, l11;
            split2(v00, h00, l00); split2(v01, h01, l01);
            split2(v10, h10, l10); split2(v11, h11, l11);
            *(__half2*)(outH + (size_t)grow * 256 + gcol) = __halves2half2(h00, h01);
            *(__half2*)(outL + (size_t)grow * 256 + gcol) = __halves2half2(l00, l01);
            *(__half2*)(outH + (size_t)(grow + 8) * 256 + gcol) = __halves2half2(h10, h11);
            *(__half2*)(outL + (size_t)(grow + 8) * 256 + gcol) = __halves2half2(l10, l11);
        }
    }
}

// ---------------- scatter for (hi,lo) fp16-pair rows of 256 ----------------
__global__ void scatter256_hl(const __half* __restrict__ hH, const __half* __restrict__ hL,
                              const int* __restrict__ src, const int* __restrict__ dst,
                              float* __restrict__ acc, float* __restrict__ cnt, int E) {
    unsigned long long gid = (unsigned long long)blockIdx.x * blockDim.x + threadIdx.x;
    unsigned e = (unsigned)(gid >> 6);
    if (e >= (unsigned)E) return;
    int lane = (int)(gid & 63);
    int s = __ldg(src + e);
    int d = __ldg(dst + e);
    const __half2* pH = (const __half2*)(hH + (size_t)s * DH + lane * 4);
    const __half2* pL = (const __half2*)(hL + (size_t)s * DH + lane * 4);
    __half2 hA = __ldg(pH), hB = __ldg(pH + 1);
    __half2 lA = __ldg(pL), lB = __ldg(pL + 1);
    float4 v;
    v.x = __half2float(__low2half(hA)) + __half2float(__low2half(lA));
    v.y = __half2float(__high2half(hA)) + __half2float(__high2half(lA));
    v.z = __half2float(__low2half(hB)) + __half2float(__low2half(lB));
    v.w = __half2float(__high2half(hB)) + __half2float(__high2half(lB));
    red_add_v4(acc + (size_t)d * DH + lane * 4, v);
    if (lane == 0) atomicAdd(cnt + d, 1.0f);
}

// ---------------- build A1 (agg scaled + self copy) ----------------
__global__ void conv1(const float* __restrict__ acc, const float* __restrict__ cnt,
                      const __half* __restrict__ hH, const __half* __restrict__ hL,
                      __half* AH, __half* AL) {
    long i = (long)blockIdx.x * blockDim.x + threadIdx.x;
    long na = (long)NN2 * 64;     // agg: 256 cols as float4 chunks
    if (i < na) {
        int r = (int)(i / 64);
        int c4 = (int)(i % 64);
        float ic = 1.0f / fmaxf(__ldg(cnt + r), 1.0f);
        float4 v = *((const float4*)(acc + (size_t)r * DH) + c4);
        float vv[4] = {v.x * ic, v.y * ic, v.z * ic, v.w * ic};
        size_t base = (size_t)r * KP1 + c4 * 4;
#pragma unroll
        for (int j = 0; j < 4; j++) {
            __half h, l;
            split2(vv[j], h, l);
            AH[base + j] = h;
            AL[base + j] = l;
        }
        return;
    }
    i -= na;
    long nb = (long)NN2 * 32;     // self copy: 256 cols as 8-half chunks
    if (i < nb) {
        int r = (int)(i / 32);
        int c8 = (int)(i % 32);
        uint4 vh = *(const uint4*)(hH + (size_t)r * DH + c8 * 8);
        uint4 vl = *(const uint4*)(hL + (size_t)r * DH + c8 * 8);
        *(uint4*)(AH + (size_t)r * KP1 + 256 + c8 * 8) = vh;
        *(uint4*)(AL + (size_t)r * KP1 + 256 + c8 * 8) = vl;
    }
}

// ---------------- final layer: GEMV K=512 + log_softmax ----------------
__global__ __launch_bounds__(64) void final_layer(
    const float* __restrict__ acc, const float* __restrict__ cnt,
    const __half* __restrict__ hH, const __half* __restrict__ hL,
    const float* __restrict__ Wl, const float* __restrict__ bias,
    const float* __restrict__ Wr, float* __restrict__ out)
{
    __shared__ float sa[DH];
    __shared__ float ss[DH];
    __shared__ float logits[DOUT];
    __shared__ float red2[2];

    const int r = blockIdx.x;
    const int t = threadIdx.x;
    float c = fmaxf(__ldg(cnt + r), 1.0f);

    for (int k = t; k < DH; k += 64) {
        sa[k] = acc[(size_t)r * DH + k] / c;
        ss[k] = __half2float(hH[(size_t)r * DH + k]) + __half2float(hL[(size_t)r * DH + k]);
    }
    __syncthreads();

    if (t < DOUT) {
        float v = __ldg(bias + t);
#pragma unroll 8
        for (int k = 0; k < DH; k++) {
            v = fmaf(sa[k], __ldg(Wl + (size_t)k * DOUT + t), v);
            v = fmaf(ss[k], __ldg(Wr + (size_t)k * DOUT + t), v);
        }
        logits[t] = v;
    }
    __syncthreads();
    if (t == 0) {
        float m = -1e30f;
        for (int i = 0; i < DOUT; i++) m = fmaxf(m, logits[i]);
        float s = 0.f;
        for (int i = 0; i < DOUT; i++) s += expf(logits[i] - m);
        red2[0] = m;
        red2[1] = logf(s);
    }
    __syncthreads();
    if (t < DOUT) out[(size_t)r * DOUT + t] = logits[t] - red2[0] - red2[1];
}

// ---------------- launch ----------------
extern "C" void kernel_launch(void* const* d_in, const int* in_sizes, int n_in,
                              void* d_out, int out_size) {
    const float* x    = (const float*)d_in[0];
    const int*   src0 = (const int*)d_in[1];
    const int*   dst0 = (const int*)d_in[2];
    const int*   src1 = (const int*)d_in[3];
    const int*   dst1 = (const int*)d_in[4];
    const int*   src2 = (const int*)d_in[5];
    const int*   dst2 = (const int*)d_in[6];
    const float* Wl0  = (const float*)d_in[7];
    const float* bl0  = (const float*)d_in[8];
    const float* Wr0  = (const float*)d_in[9];
    const float* Wl1  = (const float*)d_in[10];
    const float* bl1  = (const float*)d_in[11];
    const float* Wr1  = (const float*)d_in[12];
    const float* Wl2  = (const float*)d_in[13];
    const float* bl2  = (const float*)d_in[14];
    const float* Wr2  = (const float*)d_in[15];
    float* out = (float*)d_out;

    float* acc0 = 0; float* cnt0 = 0; float* acc1 = 0; float* cnt1 = 0;
    float* acc2 = 0; float* cnt2 = 0;
    __half* A0H = 0; __half* A0L = 0; __half* h1H = 0; __half* h1L = 0;
    __half* A1H = 0; __half* A1L = 0; __half* h2H = 0; __half* h2L = 0;
    __half* W0H = 0; __half* W0L = 0; __half* W1H = 0; __half* W1L = 0;
    cudaGetSymbolAddress((void**)&acc0, g_acc0);
    cudaGetSymbolAddress((void**)&cnt0, g_cnt0);
    cudaGetSymbolAddress((void**)&acc1, g_acc1);
    cudaGetSymbolAddress((void**)&cnt1, g_cnt1);
    cudaGetSymbolAddress((void**)&acc2, g_acc2);
    cudaGetSymbolAddress((void**)&cnt2, g_cnt2);
    cudaGetSymbolAddress((void**)&A0H, g_A0H);
    cudaGetSymbolAddress((void**)&A0L, g_A0L);
    cudaGetSymbolAddress((void**)&h1H, g_h1H);
    cudaGetSymbolAddress((void**)&h1L, g_h1L);
    cudaGetSymbolAddress((void**)&A1H, g_A1H);
    cudaGetSymbolAddress((void**)&A1L, g_A1L);
    cudaGetSymbolAddress((void**)&h2H, g_h2H);
    cudaGetSymbolAddress((void**)&h2L, g_h2L);
    cudaGetSymbolAddress((void**)&W0H, g_W0H);
    cudaGetSymbolAddress((void**)&W0L, g_W0L);
    cudaGetSymbolAddress((void**)&W1H, g_W1H);
    cudaGetSymbolAddress((void**)&W1L, g_W1L);

    cudaFuncSetAttribute(gemm_hl, cudaFuncAttributeMaxDynamicSharedMemorySize, GEMM_SMEM);

    // 0: zero accumulators
    zero_all<<<(unsigned)((ZTOT + 255) / 256), 256>>>(
        (float4*)acc0, (float4*)cnt0, (float4*)acc1,
        (float4*)cnt1, (float4*)acc2, (float4*)cnt2);

    // 1: weights
    {
        long tot = 256L * KP0 + 256L * KP1;
        conv_w_all<<<(unsigned)((tot + 255) / 256), 256>>>(Wl0, Wr0, Wl1, Wr1,
                                                           W0H, W0L, W1H, W1L);
    }
    // 2: self-part of A0 + padding
    {
        long tot = (long)NN1 * 25 + (long)NN1 * 12;
        conv_self0<<<(unsigned)((tot + 255) / 256), 256>>>(x, A0H, A0L);
    }
    // 3: layer-0 scatter
    {
        unsigned long long th = (unsigned long long)EE0 * 32;
        scatter100<<<(unsigned)((th + 255) / 256), 256>>>(x, src0, dst0, acc0, cnt0);
    }
    // 4: agg-part of A0
    {
        long tot = (long)NN1 * 25;
        conv_agg0<<<(unsigned)((tot + 255) / 256), 256>>>(acc0, cnt0, A0H, A0L);
    }
    // 5: gemm layer 0  (ncu -s 5 lands here)
    {
        dim3 g(4, NN1 / 128);
        gemm_hl<<<g, 256, GEMM_SMEM>>>(A0H, A0L, W0H, W0L, bl0, h1H, h1L, KP0);
    }
    // 6: layer-1 scatter
    {
        unsigned long long th = (unsigned long long)EE1 * 64;
        scatter256_hl<<<(unsigned)((th + 255) / 256), 256>>>(h1H, h1L, src1, dst1,
                                                             acc1, cnt1, EE1);
    }
    // 7: build A1
    {
        long tot = (long)NN2 * 64 + (long)NN2 * 32;
        conv1<<<(unsigned)((tot + 255) / 256), 256>>>(acc1, cnt1, h1H, h1L, A1H, A1L);
    }
    // 8: gemm layer 1
    {
        dim3 g(4, NN2 / 128);
        gemm_hl<<<g, 256, GEMM_SMEM>>>(A1H, A1L, W1H, W1L, bl1, h2H, h2L, KP1);
    }
    // 9: layer-2 scatter
    {
        unsigned long long th = (unsigned long long)EE2 * 64;
        scatter256_hl<<<(unsigned)((th + 255) / 256), 256>>>(h2H, h2L, src2, dst2,
                                                             acc2, cnt2, EE2);
    }
    // 10: final GEMV + log_softmax
    final_layer<<<NN3, 64>>>(acc2, cnt2, h2H, h2L, Wl2, bl2, Wr2, out);
}